// round 1
// baseline (speedup 1.0000x reference)
#include <cuda_runtime.h>
#include <math.h>

// ---------------- problem constants ----------------
#define BB 2
#define NN 32768
#define CC 512
#define HH 8
#define DH 64
#define GG 64
#define CD 256
#define ROWS (BB*NN)          // 65536
#define INNER (HH*DH)         // 512
#define EPS 1e-5f

// ---------------- scratch (device globals, no allocations) ----------------
__device__ float g_xmid [ROWS * INNER];     // 134 MB
__device__ float g_fxmid[ROWS * INNER];     // 134 MB
__device__ float g_w    [ROWS * INNER];     // 134 MB  (b,n, h*64+g)
__device__ float g_npart[256 * 512];        // per-chunk norm partials
__device__ float g_norm [BB * HH * GG];     // 1024
__device__ float g_tpart[16 * 32 * 4096];   // tokens partials (bh, chunk, g*64+d)
__device__ float g_tok  [16 * 4096];        // tokens (bh, g*64+d)
__device__ float g_ot   [16 * 4096];        // out_tok
__device__ float g_M    [BB * 512 * 512];   // folded (out_tok @ Wo)

// ============================================================
// SGEMM: C[M,N] = A[M,K] @ B[K,N] + bias[N]
// 128x128 block tile, 256 threads, 8x8 per thread, k-tile 16.
// Optional per-batch B matrix (for final GEMM with per-b M).
// ============================================================
__global__ __launch_bounds__(256) void sgemm_bias_kernel(
    const float* __restrict__ A, const float* __restrict__ B,
    const float* __restrict__ bias, float* __restrict__ C,
    int M, int N, int K, int bRowsPerBatch, int bMatStride)
{
    __shared__ float As[16][128];
    __shared__ float Bs[16][128];

    const int row0 = blockIdx.y * 128;
    const int col0 = blockIdx.x * 128;
    const float* Bp = B;
    if (bRowsPerBatch) Bp += (size_t)(row0 / bRowsPerBatch) * (size_t)bMatStride;

    const int tid = threadIdx.x;
    const int ty = tid >> 4;       // 0..15
    const int tx = tid & 15;       // 0..15

    float acc[8][8];
#pragma unroll
    for (int i = 0; i < 8; i++)
#pragma unroll
        for (int j = 0; j < 8; j++) acc[i][j] = 0.f;

    for (int k0 = 0; k0 < K; k0 += 16) {
#pragma unroll
        for (int it = 0; it < 2; it++) {
            int s = tid + it * 256;            // 0..511
            int ar  = s >> 2;                  // 0..127
            int ac4 = s & 3;                   // 0..3
            float4 av = *(const float4*)(A + (size_t)(row0 + ar) * K + k0 + ac4 * 4);
            As[ac4*4+0][ar] = av.x; As[ac4*4+1][ar] = av.y;
            As[ac4*4+2][ar] = av.z; As[ac4*4+3][ar] = av.w;
            int br  = s >> 5;                  // 0..15
            int bc4 = s & 31;                  // 0..31
            *(float4*)&Bs[br][bc4*4] =
                *(const float4*)(Bp + (size_t)(k0 + br) * N + col0 + bc4 * 4);
        }
        __syncthreads();
#pragma unroll
        for (int kk = 0; kk < 16; kk++) {
            float a[8], b[8];
            *(float4*)&a[0] = *(const float4*)&As[kk][ty*8];
            *(float4*)&a[4] = *(const float4*)&As[kk][ty*8+4];
            *(float4*)&b[0] = *(const float4*)&Bs[kk][tx*8];
            *(float4*)&b[4] = *(const float4*)&Bs[kk][tx*8+4];
#pragma unroll
            for (int i = 0; i < 8; i++)
#pragma unroll
                for (int j = 0; j < 8; j++)
                    acc[i][j] += a[i] * b[j];
        }
        __syncthreads();
    }

    float bb[8];
#pragma unroll
    for (int j = 0; j < 8; j++) bb[j] = bias[col0 + tx*8 + j];

#pragma unroll
    for (int i = 0; i < 8; i++) {
        size_t row = (size_t)row0 + ty*8 + i;
        float* Cr = C + row * (size_t)N + col0 + tx*8;
        float4 o0 = make_float4(acc[i][0]+bb[0], acc[i][1]+bb[1], acc[i][2]+bb[2], acc[i][3]+bb[3]);
        float4 o1 = make_float4(acc[i][4]+bb[4], acc[i][5]+bb[5], acc[i][6]+bb[6], acc[i][7]+bb[7]);
        *(float4*)(Cr)     = o0;
        *(float4*)(Cr + 4) = o1;
    }
}

// ============================================================
// Slice logits + softmax: w[b,n,h*64+g] from x_mid
// block = 32 tokens x 8 heads (256 threads), Wslice cached in smem
// ============================================================
__global__ __launch_bounds__(256) void slice_kernel(
    const float* __restrict__ xmid, const float* __restrict__ Wslice,
    const float* __restrict__ bslice, const float* __restrict__ temp,
    float* __restrict__ w)
{
    __shared__ float sW[4096];
    __shared__ float sb[64];
    __shared__ float sit[8];
    const int tid = threadIdx.x;
    for (int i = tid; i < 4096; i += 256) sW[i] = Wslice[i];
    if (tid < 64) sb[tid] = bslice[tid];
    if (tid < 8) {
        float t = temp[tid];
        sit[tid] = 1.0f / fminf(fmaxf(t, 0.1f), 5.0f);
    }
    __syncthreads();

    const int tok = blockIdx.x * 32 + (tid >> 3);
    const int h   = tid & 7;
    const float4* xr = (const float4*)(xmid + (size_t)tok * 512 + h * 64);

    float lg[64];
#pragma unroll
    for (int j = 0; j < 64; j++) lg[j] = sb[j];

    for (int d4 = 0; d4 < 16; d4++) {
        float4 xq = xr[d4];
        const float* w0 = &sW[(d4*4+0)*64];
        const float* w1 = &sW[(d4*4+1)*64];
        const float* w2 = &sW[(d4*4+2)*64];
        const float* w3 = &sW[(d4*4+3)*64];
#pragma unroll
        for (int j = 0; j < 64; j++)
            lg[j] += xq.x*w0[j] + xq.y*w1[j] + xq.z*w2[j] + xq.w*w3[j];
    }

    const float invt = sit[h];
    float m = -1e30f;
#pragma unroll
    for (int j = 0; j < 64; j++) { lg[j] *= invt; m = fmaxf(m, lg[j]); }
    float s = 0.f;
#pragma unroll
    for (int j = 0; j < 64; j++) { lg[j] = expf(lg[j] - m); s += lg[j]; }
    const float is = 1.0f / s;

    float* wr = w + (size_t)tok * 512 + h * 64;
#pragma unroll
    for (int j4 = 0; j4 < 16; j4++) {
        float4 o = make_float4(lg[j4*4]*is, lg[j4*4+1]*is, lg[j4*4+2]*is, lg[j4*4+3]*is);
        ((float4*)wr)[j4] = o;
    }
}

// ============================================================
// norm partials: sum w over 256-row chunks (coalesced, deterministic)
// grid 256 blocks (2 b x 128 chunks), 512 threads
// ============================================================
__global__ __launch_bounds__(512) void norm_part_kernel(
    const float* __restrict__ w, float* __restrict__ part)
{
    const int blk = blockIdx.x;
    const size_t r0 = (size_t)blk * 256;
    float s = 0.f;
    for (int r = 0; r < 256; r++)
        s += w[(r0 + r) * 512 + threadIdx.x];
    part[(size_t)blk * 512 + threadIdx.x] = s;
}

__global__ void norm_reduce_kernel(const float* __restrict__ part,
                                   float* __restrict__ norm)
{
    int e = blockIdx.x * 256 + threadIdx.x;   // 1024 entries
    int b = e >> 9, hg = e & 511;
    float s = 0.f;
    for (int c = 0; c < 128; c++)
        s += part[((size_t)(b * 128 + c)) * 512 + hg];
    norm[e] = s;
}

// ============================================================
// tokens partials: tokens[b,h,g,d] += sum_n w[n,g] * fx[n,d] over 1024-token chunk
// grid (32 chunks, 16 bh), 256 threads, 4x4 per thread
// ============================================================
__global__ __launch_bounds__(256) void tokpart_kernel(
    const float* __restrict__ fx, const float* __restrict__ w,
    float* __restrict__ part)
{
    __shared__ float ws[16][64];
    __shared__ float fs[16][64];
    const int chunk = blockIdx.x;
    const int bh = blockIdx.y;
    const int b = bh >> 3, h = bh & 7;
    const size_t rbase = (size_t)b * NN + (size_t)chunk * 1024;

    const int tid = threadIdx.x;
    const int ty = tid >> 4, tx = tid & 15;
    const int lr = tid >> 4, lc4 = tid & 15;

    float acc[4][4];
#pragma unroll
    for (int i = 0; i < 4; i++)
#pragma unroll
        for (int j = 0; j < 4; j++) acc[i][j] = 0.f;

    for (int kt = 0; kt < 1024; kt += 16) {
        size_t row = rbase + kt + lr;
        *(float4*)&ws[lr][lc4*4] = *(const float4*)(w  + row*512 + h*64 + lc4*4);
        *(float4*)&fs[lr][lc4*4] = *(const float4*)(fx + row*512 + h*64 + lc4*4);
        __syncthreads();
#pragma unroll
        for (int k = 0; k < 16; k++) {
            float4 a  = *(const float4*)&ws[k][ty*4];
            float4 bv = *(const float4*)&fs[k][tx*4];
            acc[0][0]+=a.x*bv.x; acc[0][1]+=a.x*bv.y; acc[0][2]+=a.x*bv.z; acc[0][3]+=a.x*bv.w;
            acc[1][0]+=a.y*bv.x; acc[1][1]+=a.y*bv.y; acc[1][2]+=a.y*bv.z; acc[1][3]+=a.y*bv.w;
            acc[2][0]+=a.z*bv.x; acc[2][1]+=a.z*bv.y; acc[2][2]+=a.z*bv.z; acc[2][3]+=a.z*bv.w;
            acc[3][0]+=a.w*bv.x; acc[3][1]+=a.w*bv.y; acc[3][2]+=a.w*bv.z; acc[3][3]+=a.w*bv.w;
        }
        __syncthreads();
    }

    float* p = part + ((size_t)bh * 32 + chunk) * 4096;
#pragma unroll
    for (int ig = 0; ig < 4; ig++) {
        float4 o = make_float4(acc[ig][0], acc[ig][1], acc[ig][2], acc[ig][3]);
        *(float4*)&p[(ty*4+ig)*64 + tx*4] = o;
    }
}

__global__ void tok_reduce_kernel(const float* __restrict__ part,
                                  float* __restrict__ tok)
{
    int idx = blockIdx.x * 256 + threadIdx.x;   // 65536
    int bh = idx >> 12, gd = idx & 4095;
    float s = 0.f;
    for (int c = 0; c < 32; c++)
        s += part[((size_t)bh * 32 + c) * 4096 + gd];
    tok[idx] = s;
}

// ============================================================
// tiny attention over slice tokens. 16 blocks (b,h), 64 threads (rows).
// ============================================================
__device__ __forceinline__ void row_gemm_sm(
    const float* __restrict__ xrow, int Kd,
    const float* __restrict__ W, const float* __restrict__ bias,
    float* __restrict__ outrow)
{
    float acc[64];
#pragma unroll
    for (int j = 0; j < 64; j++) acc[j] = bias[j];
    for (int d = 0; d < Kd; d++) {
        float xv = xrow[d];
        const float4* W4 = (const float4*)(W + (size_t)d * 64);
#pragma unroll
        for (int j4 = 0; j4 < 16; j4++) {
            float4 wv = W4[j4];
            acc[j4*4+0] += xv*wv.x; acc[j4*4+1] += xv*wv.y;
            acc[j4*4+2] += xv*wv.z; acc[j4*4+3] += xv*wv.w;
        }
    }
#pragma unroll
    for (int j = 0; j < 64; j++) outrow[j] = acc[j];
}

__device__ __forceinline__ void attn_row(
    const float* __restrict__ qrow, const float* __restrict__ Kt,
    const float* __restrict__ Vt, float* __restrict__ o)
{
    float qr[64];
#pragma unroll
    for (int d = 0; d < 64; d++) qr[d] = qrow[d];
    float sc[64];
    float m = -1e30f;
    for (int j = 0; j < 64; j++) {
        const float4* kr = (const float4*)(Kt + j * 64);
        float a = 0.f;
#pragma unroll
        for (int d4 = 0; d4 < 16; d4++) {
            float4 kv = kr[d4];
            a += qr[d4*4]*kv.x + qr[d4*4+1]*kv.y + qr[d4*4+2]*kv.z + qr[d4*4+3]*kv.w;
        }
        sc[j] = a * 0.125f;                    // 1/sqrt(64)
        m = fmaxf(m, sc[j]);
    }
    float s = 0.f;
#pragma unroll
    for (int j = 0; j < 64; j++) { sc[j] = expf(sc[j] - m); s += sc[j]; }
    float is = 1.0f / s;
#pragma unroll
    for (int d = 0; d < 64; d++) o[d] = 0.f;
    for (int j = 0; j < 64; j++) {
        float p = sc[j] * is;
        const float4* vr = (const float4*)(Vt + j * 64);
#pragma unroll
        for (int d4 = 0; d4 < 16; d4++) {
            float4 vv = vr[d4];
            o[d4*4+0] += p*vv.x; o[d4*4+1] += p*vv.y;
            o[d4*4+2] += p*vv.z; o[d4*4+3] += p*vv.w;
        }
    }
}

__global__ void attn_kernel(
    const float* __restrict__ ctx,
    const float* __restrict__ Wq, const float* __restrict__ bq,
    const float* __restrict__ Wk, const float* __restrict__ bk,
    const float* __restrict__ Wv, const float* __restrict__ bv,
    const float* __restrict__ Wcq, const float* __restrict__ bcq,
    const float* __restrict__ Wck, const float* __restrict__ bck,
    const float* __restrict__ Wcv, const float* __restrict__ bcv,
    const float* __restrict__ smix,
    const float* __restrict__ tokens, const float* __restrict__ norm,
    float* __restrict__ ot)
{
    extern __shared__ float sm[];
    float* s_tok = sm;
    float* s_q   = sm + 4096;
    float* s_k   = sm + 2*4096;
    float* s_v   = sm + 3*4096;
    float* s_cq  = sm + 4*4096;

    const int bh = blockIdx.x;
    const int i  = threadIdx.x;       // 0..63

    float inv = 1.0f / (norm[bh*64 + i] + EPS);
#pragma unroll 4
    for (int d = 0; d < 64; d++)
        s_tok[i*64 + d] = tokens[((size_t)bh*64 + i)*64 + d] * inv;

    // own-row projections (no cross-row reads of s_tok)
    row_gemm_sm(&s_tok[i*64], 64, Wq,  bq,  &s_q[i*64]);
    row_gemm_sm(&s_tok[i*64], 64, Wk,  bk,  &s_k[i*64]);
    row_gemm_sm(&s_tok[i*64], 64, Wv,  bv,  &s_v[i*64]);
    row_gemm_sm(&s_tok[i*64], 64, Wcq, bcq, &s_cq[i*64]);
    __syncthreads();

    float sa[64];
    attn_row(&s_q[i*64], s_k, s_v, sa);
    __syncthreads();                 // everyone done reading s_k, s_v

    // stash sa into s_tok (no longer needed), build cross K/V
#pragma unroll
    for (int d = 0; d < 64; d++) s_tok[i*64 + d] = sa[d];
    const float* crow = ctx + ((size_t)bh*64 + i) * 256;
    row_gemm_sm(crow, 256, Wck, bck, &s_q[i*64]);   // ck
    row_gemm_sm(crow, 256, Wcv, bcv, &s_k[i*64]);   // cv
    __syncthreads();

    float ca[64];
    attn_row(&s_cq[i*64], s_q, s_k, ca);

    float gmix = 1.0f / (1.0f + expf(-smix[0]));
#pragma unroll
    for (int d = 0; d < 64; d++)
        ot[((size_t)bh*64 + i)*64 + d] = gmix * s_tok[i*64 + d] + (1.0f - gmix) * ca[d];
}

// ============================================================
// M[b, h*64+g, c] = sum_d out_tok[b,h,g,d] * Wo[h*64+d, c]
// grid (4 c-tiles, 16 bh), 256 threads
// ============================================================
__global__ __launch_bounds__(256) void m_kernel(
    const float* __restrict__ Wo, const float* __restrict__ ot,
    float* __restrict__ M)
{
    __shared__ float s_ot[4096];
    __shared__ float s_wo[64 * 128];
    const int bh = blockIdx.y;
    const int h = bh & 7, b = bh >> 3;
    const int c0 = blockIdx.x * 128;
    const int tid = threadIdx.x;

    for (int idx = tid; idx < 1024; idx += 256)
        ((float4*)s_ot)[idx] = ((const float4*)(ot + (size_t)bh * 4096))[idx];
    for (int idx = tid; idx < 2048; idx += 256) {
        int d = idx >> 5;          // 32 float4 per 128-col row
        int c4 = idx & 31;
        ((float4*)s_wo)[idx] = *(const float4*)(Wo + (size_t)(h*64 + d)*512 + c0 + c4*4);
    }
    __syncthreads();

    const int g0 = (tid >> 3) * 2;      // 0..62
    const int ct = (tid & 7) * 16;      // 0..112
    float acc[2][16];
#pragma unroll
    for (int g = 0; g < 2; g++)
#pragma unroll
        for (int c = 0; c < 16; c++) acc[g][c] = 0.f;

    for (int d = 0; d < 64; d++) {
        float a0 = s_ot[g0*64 + d];
        float a1 = s_ot[(g0+1)*64 + d];
#pragma unroll
        for (int c4 = 0; c4 < 4; c4++) {
            float4 wv = *(const float4*)&s_wo[d*128 + ct + c4*4];
            acc[0][c4*4+0]+=a0*wv.x; acc[0][c4*4+1]+=a0*wv.y; acc[0][c4*4+2]+=a0*wv.z; acc[0][c4*4+3]+=a0*wv.w;
            acc[1][c4*4+0]+=a1*wv.x; acc[1][c4*4+1]+=a1*wv.y; acc[1][c4*4+2]+=a1*wv.z; acc[1][c4*4+3]+=a1*wv.w;
        }
    }

#pragma unroll
    for (int g = 0; g < 2; g++) {
        float* Mr = M + (size_t)b * 262144 + (size_t)(h*64 + g0 + g) * 512 + c0 + ct;
#pragma unroll
        for (int c4 = 0; c4 < 4; c4++)
            *(float4*)(Mr + c4*4) = make_float4(acc[g][c4*4], acc[g][c4*4+1], acc[g][c4*4+2], acc[g][c4*4+3]);
    }
}

// ============================================================
// host launcher
// ============================================================
extern "C" void kernel_launch(void* const* d_in, const int* in_sizes, int n_in,
                              void* d_out, int out_size)
{
    const float* x      = (const float*)d_in[0];
    const float* ctx    = (const float*)d_in[1];
    const float* Wx     = (const float*)d_in[2];
    const float* bx     = (const float*)d_in[3];
    const float* Wfx    = (const float*)d_in[4];
    const float* bfx    = (const float*)d_in[5];
    const float* Wslice = (const float*)d_in[6];
    const float* bslice = (const float*)d_in[7];
    const float* temp   = (const float*)d_in[8];
    const float* Wq     = (const float*)d_in[9];
    const float* bq     = (const float*)d_in[10];
    const float* Wk     = (const float*)d_in[11];
    const float* bk     = (const float*)d_in[12];
    const float* Wv     = (const float*)d_in[13];
    const float* bv     = (const float*)d_in[14];
    const float* Wcq    = (const float*)d_in[15];
    const float* bcq    = (const float*)d_in[16];
    const float* Wck    = (const float*)d_in[17];
    const float* bck    = (const float*)d_in[18];
    const float* Wcv    = (const float*)d_in[19];
    const float* bcv    = (const float*)d_in[20];
    const float* smix   = (const float*)d_in[21];
    const float* Wo     = (const float*)d_in[22];
    const float* bo     = (const float*)d_in[23];
    float* out = (float*)d_out;

    void *p;
    cudaGetSymbolAddress(&p, g_xmid);  float* xmid  = (float*)p;
    cudaGetSymbolAddress(&p, g_fxmid); float* fxmid = (float*)p;
    cudaGetSymbolAddress(&p, g_w);     float* w     = (float*)p;
    cudaGetSymbolAddress(&p, g_npart); float* npart = (float*)p;
    cudaGetSymbolAddress(&p, g_norm);  float* norm  = (float*)p;
    cudaGetSymbolAddress(&p, g_tpart); float* tpart = (float*)p;
    cudaGetSymbolAddress(&p, g_tok);   float* tok   = (float*)p;
    cudaGetSymbolAddress(&p, g_ot);    float* ot    = (float*)p;
    cudaGetSymbolAddress(&p, g_M);     float* Mm    = (float*)p;

    cudaFuncSetAttribute(attn_kernel, cudaFuncAttributeMaxDynamicSharedMemorySize, 5*4096*4);

    dim3 gemmGrid(INNER/128, ROWS/128);   // (4, 512)

    // 1,2: projections
    sgemm_bias_kernel<<<gemmGrid, 256>>>(x, Wx,  bx,  xmid,  ROWS, INNER, CC, 0, 0);
    sgemm_bias_kernel<<<gemmGrid, 256>>>(x, Wfx, bfx, fxmid, ROWS, INNER, CC, 0, 0);
    // 3: slice softmax -> w
    slice_kernel<<<ROWS/32, 256>>>(xmid, Wslice, bslice, temp, w);
    // 4,5: norm = sum_n w (deterministic two-stage)
    norm_part_kernel<<<256, 512>>>(w, npart);
    norm_reduce_kernel<<<4, 256>>>(npart, norm);
    // 6,7: tokens = w^T @ fx (deterministic two-stage)
    tokpart_kernel<<<dim3(32, 16), 256>>>(fxmid, w, tpart);
    tok_reduce_kernel<<<256, 256>>>(tpart, tok);
    // 8: tiny attention -> out_tok
    attn_kernel<<<16, 64, 5*4096*4>>>(ctx, Wq, bq, Wk, bk, Wv, bv,
                                      Wcq, bcq, Wck, bck, Wcv, bcv,
                                      smix, tok, norm, ot);
    // 9: fold out_tok @ Wo -> M
    m_kernel<<<dim3(4, 16), 256>>>(Wo, ot, Mm);
    // 10: out = w @ M[b] + bo
    sgemm_bias_kernel<<<gemmGrid, 256>>>(w, Mm, bo, out, ROWS, CC, INNER, NN, 512*512);
}

// round 2
// speedup vs baseline: 1.7698x; 1.7698x over previous
#include <cuda_runtime.h>
#include <math.h>

// ---------------- problem constants ----------------
#define BB 2
#define NN 32768
#define CC 512
#define HH 8
#define DH 64
#define GG 64
#define CD 256
#define ROWS (BB*NN)          // 65536
#define INNER (HH*DH)         // 512
#define EPS 1e-5f

// ---------------- scratch (device globals, no allocations) ----------------
__device__ float g_xmid [ROWS * INNER];
__device__ float g_fxmid[ROWS * INNER];
__device__ float g_w    [ROWS * INNER];
__device__ float g_npart[256 * 512];
__device__ float g_norm [BB * HH * GG];
__device__ float g_tpart[16 * 32 * 4096];
__device__ float g_tok  [16 * 4096];
__device__ float g_ot   [16 * 4096];
__device__ float g_M    [BB * 512 * 512];

// ============================================================
// TF32 tensor-core GEMM: C[M,N] = A[M,K] @ B[K,N] + bias[N]
// 128x128x32 block tile, 8 warps, warp tile 64x32, mma m16n8k8.
// Optional per-batch B (final GEMM: B differs per batch of rows).
// ============================================================
#define Bb_M 128
#define Bb_N 128
#define Bb_K 32
#define A_LDS 36    // padded k-stride for As[m][k]
#define B_LDS 132   // padded n-stride for Bs[k][n]

__device__ __forceinline__ unsigned f2tf(float f) {
    unsigned u;
    asm("cvt.rna.tf32.f32 %0, %1;" : "=r"(u) : "f"(f));
    return u;
}

__device__ __forceinline__ void mma_tf32(float* c, const unsigned* a, const unsigned* b) {
    asm volatile(
        "mma.sync.aligned.m16n8k8.row.col.f32.tf32.tf32.f32 "
        "{%0,%1,%2,%3},{%4,%5,%6,%7},{%8,%9},{%0,%1,%2,%3};"
        : "+f"(c[0]), "+f"(c[1]), "+f"(c[2]), "+f"(c[3])
        : "r"(a[0]), "r"(a[1]), "r"(a[2]), "r"(a[3]), "r"(b[0]), "r"(b[1]));
}

__global__ __launch_bounds__(256) void tf32_gemm_bias(
    const float* __restrict__ A, const float* __restrict__ B,
    const float* __restrict__ bias, float* __restrict__ C,
    int M, int N, int K, int bRowsPerBatch, int bMatStride)
{
    __shared__ unsigned As[Bb_M * A_LDS];   // [m][k] padded
    __shared__ unsigned Bs[Bb_K * B_LDS];   // [k][n] padded

    const int tid  = threadIdx.x;
    const int lane = tid & 31;
    const int warp = tid >> 5;
    const int wr   = warp >> 2;    // 0..1 (m)
    const int wc   = warp & 3;     // 0..3 (n)
    const int row0 = blockIdx.y * Bb_M;
    const int col0 = blockIdx.x * Bb_N;

    const float* Bp = B;
    if (bRowsPerBatch) Bp += (size_t)(row0 / bRowsPerBatch) * (size_t)bMatStride;

    float c[4][4][4];
#pragma unroll
    for (int i = 0; i < 4; i++)
#pragma unroll
        for (int j = 0; j < 4; j++)
#pragma unroll
            for (int r = 0; r < 4; r++) c[i][j][r] = 0.f;

    const int g = lane >> 2;   // 0..7
    const int t = lane & 3;    // 0..3

    for (int k0 = 0; k0 < K; k0 += Bb_K) {
        // ---- stage A tile (128 x 32), convert to tf32, layout [m][k] ----
#pragma unroll
        for (int it = 0; it < 4; it++) {
            int s  = tid + it * 256;           // 0..1023
            int r  = s >> 3;                   // 0..127
            int kc = (s & 7) * 4;              // 0..28
            float4 v = *(const float4*)(A + (size_t)(row0 + r) * K + k0 + kc);
            unsigned* d = &As[r * A_LDS + kc];
            d[0] = f2tf(v.x); d[1] = f2tf(v.y); d[2] = f2tf(v.z); d[3] = f2tf(v.w);
        }
        // ---- stage B tile (32 x 128), layout [k][n] ----
#pragma unroll
        for (int it = 0; it < 4; it++) {
            int s  = tid + it * 256;
            int kr = s >> 5;                   // 0..31
            int nc = (s & 31) * 4;             // 0..124
            float4 v = *(const float4*)(Bp + (size_t)(k0 + kr) * N + col0 + nc);
            unsigned* d = &Bs[kr * B_LDS + nc];
            d[0] = f2tf(v.x); d[1] = f2tf(v.y); d[2] = f2tf(v.z); d[3] = f2tf(v.w);
        }
        __syncthreads();

#pragma unroll
        for (int ks = 0; ks < 4; ks++) {
            const int kb = ks * 8;
            unsigned a[4][4], b[4][2];
#pragma unroll
            for (int i = 0; i < 4; i++) {
                int rm = wr * 64 + i * 16 + g;
                a[i][0] = As[rm * A_LDS + kb + t];
                a[i][1] = As[(rm + 8) * A_LDS + kb + t];
                a[i][2] = As[rm * A_LDS + kb + t + 4];
                a[i][3] = As[(rm + 8) * A_LDS + kb + t + 4];
            }
#pragma unroll
            for (int j = 0; j < 4; j++) {
                int nb = wc * 32 + j * 8 + g;
                b[j][0] = Bs[(kb + t) * B_LDS + nb];
                b[j][1] = Bs[(kb + t + 4) * B_LDS + nb];
            }
#pragma unroll
            for (int i = 0; i < 4; i++)
#pragma unroll
                for (int j = 0; j < 4; j++)
                    mma_tf32(c[i][j], a[i], b[j]);
        }
        __syncthreads();
    }

    // ---- epilogue: bias add + store ----
#pragma unroll
    for (int i = 0; i < 4; i++) {
        int rm = row0 + wr * 64 + i * 16 + g;
#pragma unroll
        for (int j = 0; j < 4; j++) {
            int cn = col0 + wc * 32 + j * 8 + t * 2;
            float b0 = bias[cn], b1 = bias[cn + 1];
            *(float2*)(C + (size_t)rm * N + cn) =
                make_float2(c[i][j][0] + b0, c[i][j][1] + b1);
            *(float2*)(C + (size_t)(rm + 8) * N + cn) =
                make_float2(c[i][j][2] + b0, c[i][j][3] + b1);
        }
    }
}

// ============================================================
// Slice logits + softmax: w[b,n,h*64+g] from x_mid
// ============================================================
__global__ __launch_bounds__(256) void slice_kernel(
    const float* __restrict__ xmid, const float* __restrict__ Wslice,
    const float* __restrict__ bslice, const float* __restrict__ temp,
    float* __restrict__ w)
{
    __shared__ float sW[4096];
    __shared__ float sb[64];
    __shared__ float sit[8];
    const int tid = threadIdx.x;
    for (int i = tid; i < 4096; i += 256) sW[i] = Wslice[i];
    if (tid < 64) sb[tid] = bslice[tid];
    if (tid < 8) {
        float t = temp[tid];
        sit[tid] = 1.0f / fminf(fmaxf(t, 0.1f), 5.0f);
    }
    __syncthreads();

    const int tok = blockIdx.x * 32 + (tid >> 3);
    const int h   = tid & 7;
    const float4* xr = (const float4*)(xmid + (size_t)tok * 512 + h * 64);

    float lg[64];
#pragma unroll
    for (int j = 0; j < 64; j++) lg[j] = sb[j];

    for (int d4 = 0; d4 < 16; d4++) {
        float4 xq = xr[d4];
        const float* w0 = &sW[(d4*4+0)*64];
        const float* w1 = &sW[(d4*4+1)*64];
        const float* w2 = &sW[(d4*4+2)*64];
        const float* w3 = &sW[(d4*4+3)*64];
#pragma unroll
        for (int j = 0; j < 64; j++)
            lg[j] += xq.x*w0[j] + xq.y*w1[j] + xq.z*w2[j] + xq.w*w3[j];
    }

    const float invt = sit[h];
    float m = -1e30f;
#pragma unroll
    for (int j = 0; j < 64; j++) { lg[j] *= invt; m = fmaxf(m, lg[j]); }
    float s = 0.f;
#pragma unroll
    for (int j = 0; j < 64; j++) { lg[j] = expf(lg[j] - m); s += lg[j]; }
    const float is = 1.0f / s;

    float* wr = w + (size_t)tok * 512 + h * 64;
#pragma unroll
    for (int j4 = 0; j4 < 16; j4++) {
        float4 o = make_float4(lg[j4*4]*is, lg[j4*4+1]*is, lg[j4*4+2]*is, lg[j4*4+3]*is);
        ((float4*)wr)[j4] = o;
    }
}

// ============================================================
// norm: two-stage deterministic column sums of w
// ============================================================
__global__ __launch_bounds__(512) void norm_part_kernel(
    const float* __restrict__ w, float* __restrict__ part)
{
    const int blk = blockIdx.x;
    const size_t r0 = (size_t)blk * 256;
    float s = 0.f;
    for (int r = 0; r < 256; r++)
        s += w[(r0 + r) * 512 + threadIdx.x];
    part[(size_t)blk * 512 + threadIdx.x] = s;
}

__global__ void norm_reduce_kernel(const float* __restrict__ part,
                                   float* __restrict__ norm)
{
    int e = blockIdx.x * 256 + threadIdx.x;
    int b = e >> 9, hg = e & 511;
    float s = 0.f;
    for (int c = 0; c < 128; c++)
        s += part[((size_t)(b * 128 + c)) * 512 + hg];
    norm[e] = s;
}

// ============================================================
// tokens partials: tokens[b,h,g,d] = sum_n w[n,g]*fx[n,d], chunked
// ============================================================
__global__ __launch_bounds__(256) void tokpart_kernel(
    const float* __restrict__ fx, const float* __restrict__ w,
    float* __restrict__ part)
{
    __shared__ float ws[16][64];
    __shared__ float fs[16][64];
    const int chunk = blockIdx.x;
    const int bh = blockIdx.y;
    const int b = bh >> 3, h = bh & 7;
    const size_t rbase = (size_t)b * NN + (size_t)chunk * 1024;

    const int tid = threadIdx.x;
    const int ty = tid >> 4, tx = tid & 15;
    const int lr = tid >> 4, lc4 = tid & 15;

    float acc[4][4];
#pragma unroll
    for (int i = 0; i < 4; i++)
#pragma unroll
        for (int j = 0; j < 4; j++) acc[i][j] = 0.f;

    for (int kt = 0; kt < 1024; kt += 16) {
        size_t row = rbase + kt + lr;
        *(float4*)&ws[lr][lc4*4] = *(const float4*)(w  + row*512 + h*64 + lc4*4);
        *(float4*)&fs[lr][lc4*4] = *(const float4*)(fx + row*512 + h*64 + lc4*4);
        __syncthreads();
#pragma unroll
        for (int k = 0; k < 16; k++) {
            float4 a  = *(const float4*)&ws[k][ty*4];
            float4 bv = *(const float4*)&fs[k][tx*4];
            acc[0][0]+=a.x*bv.x; acc[0][1]+=a.x*bv.y; acc[0][2]+=a.x*bv.z; acc[0][3]+=a.x*bv.w;
            acc[1][0]+=a.y*bv.x; acc[1][1]+=a.y*bv.y; acc[1][2]+=a.y*bv.z; acc[1][3]+=a.y*bv.w;
            acc[2][0]+=a.z*bv.x; acc[2][1]+=a.z*bv.y; acc[2][2]+=a.z*bv.z; acc[2][3]+=a.z*bv.w;
            acc[3][0]+=a.w*bv.x; acc[3][1]+=a.w*bv.y; acc[3][2]+=a.w*bv.z; acc[3][3]+=a.w*bv.w;
        }
        __syncthreads();
    }

    float* p = part + ((size_t)bh * 32 + chunk) * 4096;
#pragma unroll
    for (int ig = 0; ig < 4; ig++) {
        float4 o = make_float4(acc[ig][0], acc[ig][1], acc[ig][2], acc[ig][3]);
        *(float4*)&p[(ty*4+ig)*64 + tx*4] = o;
    }
}

__global__ void tok_reduce_kernel(const float* __restrict__ part,
                                  float* __restrict__ tok)
{
    int idx = blockIdx.x * 256 + threadIdx.x;
    int bh = idx >> 12, gd = idx & 4095;
    float s = 0.f;
    for (int c = 0; c < 32; c++)
        s += part[((size_t)bh * 32 + c) * 4096 + gd];
    tok[idx] = s;
}

// ============================================================
// tiny attention over slice tokens
// ============================================================
__device__ __forceinline__ void row_gemm_sm(
    const float* __restrict__ xrow, int Kd,
    const float* __restrict__ W, const float* __restrict__ bias,
    float* __restrict__ outrow)
{
    float acc[64];
#pragma unroll
    for (int j = 0; j < 64; j++) acc[j] = bias[j];
    for (int d = 0; d < Kd; d++) {
        float xv = xrow[d];
        const float4* W4 = (const float4*)(W + (size_t)d * 64);
#pragma unroll
        for (int j4 = 0; j4 < 16; j4++) {
            float4 wv = W4[j4];
            acc[j4*4+0] += xv*wv.x; acc[j4*4+1] += xv*wv.y;
            acc[j4*4+2] += xv*wv.z; acc[j4*4+3] += xv*wv.w;
        }
    }
#pragma unroll
    for (int j = 0; j < 64; j++) outrow[j] = acc[j];
}

__device__ __forceinline__ void attn_row(
    const float* __restrict__ qrow, const float* __restrict__ Kt,
    const float* __restrict__ Vt, float* __restrict__ o)
{
    float qr[64];
#pragma unroll
    for (int d = 0; d < 64; d++) qr[d] = qrow[d];
    float sc[64];
    float m = -1e30f;
    for (int j = 0; j < 64; j++) {
        const float4* kr = (const float4*)(Kt + j * 64);
        float a = 0.f;
#pragma unroll
        for (int d4 = 0; d4 < 16; d4++) {
            float4 kv = kr[d4];
            a += qr[d4*4]*kv.x + qr[d4*4+1]*kv.y + qr[d4*4+2]*kv.z + qr[d4*4+3]*kv.w;
        }
        sc[j] = a * 0.125f;
        m = fmaxf(m, sc[j]);
    }
    float s = 0.f;
#pragma unroll
    for (int j = 0; j < 64; j++) { sc[j] = expf(sc[j] - m); s += sc[j]; }
    float is = 1.0f / s;
#pragma unroll
    for (int d = 0; d < 64; d++) o[d] = 0.f;
    for (int j = 0; j < 64; j++) {
        float p = sc[j] * is;
        const float4* vr = (const float4*)(Vt + j * 64);
#pragma unroll
        for (int d4 = 0; d4 < 16; d4++) {
            float4 vv = vr[d4];
            o[d4*4+0] += p*vv.x; o[d4*4+1] += p*vv.y;
            o[d4*4+2] += p*vv.z; o[d4*4+3] += p*vv.w;
        }
    }
}

__global__ void attn_kernel(
    const float* __restrict__ ctx,
    const float* __restrict__ Wq, const float* __restrict__ bq,
    const float* __restrict__ Wk, const float* __restrict__ bk,
    const float* __restrict__ Wv, const float* __restrict__ bv,
    const float* __restrict__ Wcq, const float* __restrict__ bcq,
    const float* __restrict__ Wck, const float* __restrict__ bck,
    const float* __restrict__ Wcv, const float* __restrict__ bcv,
    const float* __restrict__ smix,
    const float* __restrict__ tokens, const float* __restrict__ norm,
    float* __restrict__ ot)
{
    extern __shared__ float sm[];
    float* s_tok = sm;
    float* s_q   = sm + 4096;
    float* s_k   = sm + 2*4096;
    float* s_v   = sm + 3*4096;
    float* s_cq  = sm + 4*4096;

    const int bh = blockIdx.x;
    const int i  = threadIdx.x;

    float inv = 1.0f / (norm[bh*64 + i] + EPS);
#pragma unroll 4
    for (int d = 0; d < 64; d++)
        s_tok[i*64 + d] = tokens[((size_t)bh*64 + i)*64 + d] * inv;

    row_gemm_sm(&s_tok[i*64], 64, Wq,  bq,  &s_q[i*64]);
    row_gemm_sm(&s_tok[i*64], 64, Wk,  bk,  &s_k[i*64]);
    row_gemm_sm(&s_tok[i*64], 64, Wv,  bv,  &s_v[i*64]);
    row_gemm_sm(&s_tok[i*64], 64, Wcq, bcq, &s_cq[i*64]);
    __syncthreads();

    float sa[64];
    attn_row(&s_q[i*64], s_k, s_v, sa);
    __syncthreads();

#pragma unroll
    for (int d = 0; d < 64; d++) s_tok[i*64 + d] = sa[d];
    const float* crow = ctx + ((size_t)bh*64 + i) * 256;
    row_gemm_sm(crow, 256, Wck, bck, &s_q[i*64]);
    row_gemm_sm(crow, 256, Wcv, bcv, &s_k[i*64]);
    __syncthreads();

    float ca[64];
    attn_row(&s_cq[i*64], s_q, s_k, ca);

    float gmix = 1.0f / (1.0f + expf(-smix[0]));
#pragma unroll
    for (int d = 0; d < 64; d++)
        ot[((size_t)bh*64 + i)*64 + d] = gmix * s_tok[i*64 + d] + (1.0f - gmix) * ca[d];
}

// ============================================================
// M[b, h*64+g, c] = sum_d out_tok[b,h,g,d] * Wo[h*64+d, c]
// ============================================================
__global__ __launch_bounds__(256) void m_kernel(
    const float* __restrict__ Wo, const float* __restrict__ ot,
    float* __restrict__ M)
{
    __shared__ float s_ot[4096];
    __shared__ float s_wo[64 * 128];
    const int bh = blockIdx.y;
    const int h = bh & 7, b = bh >> 3;
    const int c0 = blockIdx.x * 128;
    const int tid = threadIdx.x;

    for (int idx = tid; idx < 1024; idx += 256)
        ((float4*)s_ot)[idx] = ((const float4*)(ot + (size_t)bh * 4096))[idx];
    for (int idx = tid; idx < 2048; idx += 256) {
        int d = idx >> 5;
        int c4 = idx & 31;
        ((float4*)s_wo)[idx] = *(const float4*)(Wo + (size_t)(h*64 + d)*512 + c0 + c4*4);
    }
    __syncthreads();

    const int g0 = (tid >> 3) * 2;
    const int ct = (tid & 7) * 16;
    float acc[2][16];
#pragma unroll
    for (int g = 0; g < 2; g++)
#pragma unroll
        for (int c = 0; c < 16; c++) acc[g][c] = 0.f;

    for (int d = 0; d < 64; d++) {
        float a0 = s_ot[g0*64 + d];
        float a1 = s_ot[(g0+1)*64 + d];
#pragma unroll
        for (int c4 = 0; c4 < 4; c4++) {
            float4 wv = *(const float4*)&s_wo[d*128 + ct + c4*4];
            acc[0][c4*4+0]+=a0*wv.x; acc[0][c4*4+1]+=a0*wv.y; acc[0][c4*4+2]+=a0*wv.z; acc[0][c4*4+3]+=a0*wv.w;
            acc[1][c4*4+0]+=a1*wv.x; acc[1][c4*4+1]+=a1*wv.y; acc[1][c4*4+2]+=a1*wv.z; acc[1][c4*4+3]+=a1*wv.w;
        }
    }

#pragma unroll
    for (int g = 0; g < 2; g++) {
        float* Mr = M + (size_t)b * 262144 + (size_t)(h*64 + g0 + g) * 512 + c0 + ct;
#pragma unroll
        for (int c4 = 0; c4 < 4; c4++)
            *(float4*)(Mr + c4*4) = make_float4(acc[g][c4*4], acc[g][c4*4+1], acc[g][c4*4+2], acc[g][c4*4+3]);
    }
}

// ============================================================
// host launcher
// ============================================================
extern "C" void kernel_launch(void* const* d_in, const int* in_sizes, int n_in,
                              void* d_out, int out_size)
{
    const float* x      = (const float*)d_in[0];
    const float* ctx    = (const float*)d_in[1];
    const float* Wx     = (const float*)d_in[2];
    const float* bx     = (const float*)d_in[3];
    const float* Wfx    = (const float*)d_in[4];
    const float* bfx    = (const float*)d_in[5];
    const float* Wslice = (const float*)d_in[6];
    const float* bslice = (const float*)d_in[7];
    const float* temp   = (const float*)d_in[8];
    const float* Wq     = (const float*)d_in[9];
    const float* bq     = (const float*)d_in[10];
    const float* Wk     = (const float*)d_in[11];
    const float* bk     = (const float*)d_in[12];
    const float* Wv     = (const float*)d_in[13];
    const float* bv     = (const float*)d_in[14];
    const float* Wcq    = (const float*)d_in[15];
    const float* bcq    = (const float*)d_in[16];
    const float* Wck    = (const float*)d_in[17];
    const float* bck    = (const float*)d_in[18];
    const float* Wcv    = (const float*)d_in[19];
    const float* bcv    = (const float*)d_in[20];
    const float* smix   = (const float*)d_in[21];
    const float* Wo     = (const float*)d_in[22];
    const float* bo     = (const float*)d_in[23];
    float* out = (float*)d_out;

    void *p;
    cudaGetSymbolAddress(&p, g_xmid);  float* xmid  = (float*)p;
    cudaGetSymbolAddress(&p, g_fxmid); float* fxmid = (float*)p;
    cudaGetSymbolAddress(&p, g_w);     float* w     = (float*)p;
    cudaGetSymbolAddress(&p, g_npart); float* npart = (float*)p;
    cudaGetSymbolAddress(&p, g_norm);  float* norm  = (float*)p;
    cudaGetSymbolAddress(&p, g_tpart); float* tpart = (float*)p;
    cudaGetSymbolAddress(&p, g_tok);   float* tok   = (float*)p;
    cudaGetSymbolAddress(&p, g_ot);    float* ot    = (float*)p;
    cudaGetSymbolAddress(&p, g_M);     float* Mm    = (float*)p;

    cudaFuncSetAttribute(attn_kernel, cudaFuncAttributeMaxDynamicSharedMemorySize, 5*4096*4);

    dim3 gemmGrid(INNER/128, ROWS/128);   // (4, 512)

    // 1,2: projections (TF32 tensor cores)
    tf32_gemm_bias<<<gemmGrid, 256>>>(x, Wx,  bx,  xmid,  ROWS, INNER, CC, 0, 0);
    tf32_gemm_bias<<<gemmGrid, 256>>>(x, Wfx, bfx, fxmid, ROWS, INNER, CC, 0, 0);
    // 3: slice softmax -> w
    slice_kernel<<<ROWS/32, 256>>>(xmid, Wslice, bslice, temp, w);
    // 4,5: norm (deterministic two-stage)
    norm_part_kernel<<<256, 512>>>(w, npart);
    norm_reduce_kernel<<<4, 256>>>(npart, norm);
    // 6,7: tokens = w^T @ fx (deterministic two-stage)
    tokpart_kernel<<<dim3(32, 16), 256>>>(fxmid, w, tpart);
    tok_reduce_kernel<<<256, 256>>>(tpart, tok);
    // 8: tiny attention -> out_tok
    attn_kernel<<<16, 64, 5*4096*4>>>(ctx, Wq, bq, Wk, bk, Wv, bv,
                                      Wcq, bcq, Wck, bck, Wcv, bcv,
                                      smix, tok, norm, ot);
    // 9: fold out_tok @ Wo -> M
    m_kernel<<<dim3(4, 16), 256>>>(Wo, ot, Mm);
    // 10: out = w @ M[b] + bo (TF32 tensor cores, per-batch B)
    tf32_gemm_bias<<<gemmGrid, 256>>>(w, Mm, bo, out, ROWS, CC, INNER, NN, 512*512);
}